// round 4
// baseline (speedup 1.0000x reference)
#include <cuda_runtime.h>

// CreateOverlappingWindows: x (B=64, T=2000, C=26) fp32 ->
// out (B*T, 19*26), N_CONTEXT=9, zero-padded edges.
//
// Identity: out row (b,t) is the CONTIGUOUS x slice x[b, t-9 : t+10, :]
// flattened (494 floats), rows sliding by 26 floats. So no staging at all:
// direct LDG (L1-resident, ~7KB footprint per block) -> STG.
//
// Flat tile offset fe: trow = fe/494, src p = (t0-9)*26 + fe - trow*468,
// valid iff (unsigned)p < 52000 (p = t*26 + c, c < 26 -> equivalent to
// 0 <= t < 2000). float2 never crosses an x row (26 even) nor an output
// row (494 even), so float2 granularity is crossing-free both sides.

#define B_DIM   64
#define T_DIM   2000
#define C_DIM   26
#define NCTX    9
#define WINDOW  19
#define ROW_F   (WINDOW * C_DIM)          // 494
#define XROW_F  (T_DIM * C_DIM)           // 52000 floats per batch
#define TILE_T  50                         // output rows per block
#define TILE_F2 (TILE_T * ROW_F / 2)       // 12350 float2 per tile
#define NTHREADS 256

__global__ __launch_bounds__(NTHREADS) void overlap_windows_kernel(
    const float* __restrict__ x, float* __restrict__ out)
{
    const int tile = blockIdx.x;          // 0..39
    const int b    = blockIdx.y;          // 0..63
    const int t0   = tile * TILE_T;
    const int tid  = threadIdx.x;

    const float* xb = x + (size_t)b * XROW_F;
    float* tout = out + ((size_t)b * T_DIM + t0) * ROW_F;
    const int s0 = (t0 - NCTX) * C_DIM;   // may be negative (tile 0)

    #pragma unroll 4
    for (int i2 = tid; i2 < TILE_F2; i2 += NTHREADS) {
        const int fe   = i2 * 2;
        const int trow = fe / ROW_F;                  // mul-hi divide
        const int p    = s0 + fe - trow * (ROW_F - C_DIM);
        float2 v = make_float2(0.0f, 0.0f);
        if ((unsigned)p < (unsigned)XROW_F) {
            v = *reinterpret_cast<const float2*>(xb + p);
        }
        __stcs(reinterpret_cast<float2*>(tout + fe), v);
    }
}

extern "C" void kernel_launch(void* const* d_in, const int* in_sizes, int n_in,
                              void* d_out, int out_size)
{
    const float* x = (const float*)d_in[0];
    float* out = (float*)d_out;

    dim3 grid(T_DIM / TILE_T, B_DIM);     // 40 x 64 = 2560 blocks
    overlap_windows_kernel<<<grid, NTHREADS>>>(x, out);
}

// round 5
// speedup vs baseline: 1.0177x; 1.0177x over previous
#include <cuda_runtime.h>

// CreateOverlappingWindows: x (B=64, T=2000, C=26) fp32 ->
// out (B*T, 19*26), N_CONTEXT=9, zero-padded edges.
//
// out row (b,t) = contiguous x slice x[b, t-9 : t+10, :] flattened.
// Direct gather: 2x LDG.64 (L1-resident source) -> 1x STG.128 (flat,
// fully coalesced, streaming). float4 stores are fine across output-row
// boundaries because the output is flat-contiguous; only the SOURCE
// address changes per float2 half, computed independently.
//
// src for flat tile offset fe: trow = fe/494, p = s0 + fe - trow*468,
// valid iff (unsigned)p < 52000.

#define B_DIM   64
#define T_DIM   2000
#define C_DIM   26
#define NCTX    9
#define WINDOW  19
#define ROW_F   (WINDOW * C_DIM)          // 494
#define SLIDE   (ROW_F - C_DIM)           // 468
#define XROW_F  (T_DIM * C_DIM)           // 52000 floats per batch
#define TILE_T  50                         // output rows per block
#define TILE_F4 (TILE_T * ROW_F / 4)       // 6175 float4 per tile
#define NTHREADS 256

__global__ __launch_bounds__(NTHREADS) void overlap_windows_kernel(
    const float* __restrict__ x, float* __restrict__ out)
{
    const int tile = blockIdx.x;          // 0..39
    const int b    = blockIdx.y;          // 0..63
    const int t0   = tile * TILE_T;
    const int tid  = threadIdx.x;

    const float* xb = x + (size_t)b * XROW_F;
    float* tout = out + ((size_t)b * T_DIM + t0) * ROW_F;  // 16B aligned
    const int s0 = (t0 - NCTX) * C_DIM;   // may be negative (tile 0)

    #pragma unroll 4
    for (int i4 = tid; i4 < TILE_F4; i4 += NTHREADS) {
        const int fe = i4 * 4;

        // first float2 half
        const int trow0 = fe / ROW_F;
        const int p0    = s0 + fe - trow0 * SLIDE;
        // second float2 half (fe+2 may be in the next output row)
        const int trow1 = (fe + 2) / ROW_F;
        const int p1    = s0 + (fe + 2) - trow1 * SLIDE;

        float2 a = make_float2(0.0f, 0.0f);
        float2 c = make_float2(0.0f, 0.0f);
        if ((unsigned)p0 < (unsigned)XROW_F)
            a = *reinterpret_cast<const float2*>(xb + p0);
        if ((unsigned)p1 < (unsigned)XROW_F)
            c = *reinterpret_cast<const float2*>(xb + p1);

        const float4 v = make_float4(a.x, a.y, c.x, c.y);
        __stcs(reinterpret_cast<float4*>(tout + fe), v);
    }
}

extern "C" void kernel_launch(void* const* d_in, const int* in_sizes, int n_in,
                              void* d_out, int out_size)
{
    const float* x = (const float*)d_in[0];
    float* out = (float*)d_out;

    dim3 grid(T_DIM / TILE_T, B_DIM);     // 40 x 64 = 2560 blocks
    overlap_windows_kernel<<<grid, NTHREADS>>>(x, out);
}